// round 4
// baseline (speedup 1.0000x reference)
#include <cuda_runtime.h>

// out[b, o, f] = sum_t x[b, t, f] * W[f, o, t] + bias[f, o],  f < TGT=2
// x: (4096, 24, 256) f32   W: (256, 24, 24) f32   bias: (256, 24) f32
// out: (4096, 24, 2) f32 -> viewed as float2 out2[b*24 + o]

#define B_DIM 4096
#define T_DIM 24
#define F_DIM 256
#define O_DIM 24
#define NPAIR (B_DIM * O_DIM)        // 98304 (b,o) pairs, one per thread
#define BLOCK 256

__global__ __launch_bounds__(BLOCK) void dlinear_kernel(
    const float* __restrict__ x,
    const float* __restrict__ W,
    const float* __restrict__ bias,
    float2* __restrict__ out2)
{
    // Wt[t][o] = (W[0,o,t], W[1,o,t]); consecutive o -> consecutive float2
    // => LDS.64 with lanes o,o+1,... fully conflict-free.
    __shared__ float2 Wt[T_DIM * O_DIM];   // 24*24 float2 = 4.5KB
    __shared__ float2 bs[O_DIM];           // (bias[0,o], bias[1,o])

    const int tid = threadIdx.x;
    const int i   = blockIdx.x * BLOCK + tid;   // (b,o) pair index
    const int b   = i / O_DIM;
    const int o   = i - b * O_DIM;

    // ---- Issue all 24 x loads immediately (independent, MLP=24/thread).
    // Each is the front 8B of a 1KB row; lanes sharing b broadcast-dedup.
    const float2* __restrict__ x2 = (const float2*)x;
    float2 xv[T_DIM];
    #pragma unroll
    for (int t = 0; t < T_DIM; t++)
        xv[t] = __ldg(x2 + (size_t)(b * T_DIM + t) * (F_DIM / 2));

    // ---- Overlapped: stage W (transposed) + bias into smem.
    #pragma unroll
    for (int j = tid; j < O_DIM * T_DIM; j += BLOCK) {
        int wo = j / T_DIM;
        int wt = j - wo * T_DIM;
        Wt[wt * O_DIM + wo] = make_float2(W[j], W[O_DIM * T_DIM + j]);
    }
    if (tid < O_DIM)
        bs[tid] = make_float2(bias[tid], bias[O_DIM + tid]);
    __syncthreads();

    // ---- Compute both outputs for (b,o): 24 LDS.64 + 48 FMA.
    float2 acc = bs[o];
    #pragma unroll
    for (int t = 0; t < T_DIM; t++) {
        float2 w = Wt[t * O_DIM + o];
        acc.x = fmaf(xv[t].x, w.x, acc.x);
        acc.y = fmaf(xv[t].y, w.y, acc.y);
    }

    out2[i] = acc;   // coalesced 8B stores
}

extern "C" void kernel_launch(void* const* d_in, const int* in_sizes, int n_in,
                              void* d_out, int out_size)
{
    const float* x    = (const float*)d_in[0];
    const float* W    = (const float*)d_in[1];
    const float* bias = (const float*)d_in[2];
    float2* out2 = (float2*)d_out;

    dim3 grid(NPAIR / BLOCK);   // 384 blocks
    dlinear_kernel<<<grid, BLOCK>>>(x, W, bias, out2);
}

// round 5
// speedup vs baseline: 1.2857x; 1.2857x over previous
#include <cuda_runtime.h>

// out[b, o, f] = sum_t x[b, t, f] * W[f, o, t] + bias[f, o],  f < TGT=2
// x: (4096, 24, 256) f32   W: (256, 24, 24) f32   bias: (256, 24) f32
// out: (4096, 24, 2) f32 -> float2 out2[b*24 + o]

#define B_DIM 4096
#define T_DIM 24
#define F_DIM 256
#define O_DIM 24
#define NB    16                      // batch rows per block
#define BLOCK 384                     // == NB*T_DIM (1 gather/thread) == NB*O_DIM (1 output/thread)
#define GRID  (B_DIM / NB)            // 256 blocks

__global__ __launch_bounds__(BLOCK) void dlinear_kernel(
    const float* __restrict__ x,
    const float* __restrict__ W,
    const float* __restrict__ bias,
    float2* __restrict__ out2)
{
    __shared__ float2 xs[NB * T_DIM];      // xs[b_l*24 + t] = (x_f0, x_f1)
    __shared__ float2 Wt[T_DIM * O_DIM];   // Wt[t*24 + o] = (W[0,o,t], W[1,o,t])
    __shared__ float2 bs[O_DIM];           // (bias[0,o], bias[1,o])

    const int tid = threadIdx.x;
    const int b0  = blockIdx.x * NB;

    // ---- Phase 1a: gather x — exactly one float2 per thread, every lane a
    // DISTINCT 128B line (front 8B of each 1KB x row).
    {
        const float2* __restrict__ x2 = (const float2*)x;
        int b_l = tid / T_DIM;
        int t   = tid - b_l * T_DIM;
        xs[tid] = __ldg(x2 + (size_t)((b0 + b_l) * T_DIM + t) * (F_DIM / 2));
    }

    // ---- Phase 1b (overlapped): stage W transposed as float2 + bias.
    #pragma unroll
    for (int j = tid; j < O_DIM * T_DIM; j += BLOCK) {
        int wo = j / T_DIM;
        int wt = j - wo * T_DIM;
        Wt[wt * O_DIM + wo] = make_float2(W[j], W[O_DIM * T_DIM + j]);
    }
    if (tid < O_DIM)
        bs[tid] = make_float2(bias[tid], bias[O_DIM + tid]);
    __syncthreads();

    // ---- Phase 2: one (b_l, o) float2 output per thread.
    // x reads: 24 lanes share b_l -> broadcast; w reads: consecutive o -> conflict-free.
    const int b_l = tid / O_DIM;
    const int o   = tid - b_l * O_DIM;

    const float2* xrow = xs + b_l * T_DIM;

    float2 acc = bs[o];
    #pragma unroll
    for (int t = 0; t < T_DIM; t++) {
        float2 xv = xrow[t];
        float2 w  = Wt[t * O_DIM + o];
        acc.x = fmaf(xv.x, w.x, acc.x);
        acc.y = fmaf(xv.y, w.y, acc.y);
    }

    out2[(size_t)b0 * O_DIM + tid] = acc;   // coalesced STG.64
}

extern "C" void kernel_launch(void* const* d_in, const int* in_sizes, int n_in,
                              void* d_out, int out_size)
{
    const float* x    = (const float*)d_in[0];
    const float* W    = (const float*)d_in[1];
    const float* bias = (const float*)d_in[2];
    float2* out2 = (float2*)d_out;

    dlinear_kernel<<<GRID, BLOCK>>>(x, W, bias, out2);
}

// round 6
// speedup vs baseline: 1.3478x; 1.0483x over previous
#include <cuda_runtime.h>

// out[b, o, f] = sum_t x[b, t, f] * W[f, o, t] + bias[f, o],  f < TGT=2
// x: (4096, 24, 256) f32   W: (256, 24, 24) f32   bias: (256, 24) f32
// out: (4096, 24, 2) f32 -> float2 out2[b*24 + o]

#define B_DIM 4096
#define T_DIM 24
#define F_DIM 256
#define O_DIM 24
#define NB    8                       // batch rows per block
#define BLOCK 192                     // == NB*T_DIM (1 gather/thread) == NB*O_DIM (1 float2 output/thread)
#define GRID  (B_DIM / NB)            // 512 blocks
#define WJ    12                      // 24 (w0,w1) pairs = 12 float4 per o
#define WPAD  13                      // pad stride to 13 float4 -> conflict-free LDS.128

__global__ __launch_bounds__(BLOCK) void dlinear_kernel(
    const float* __restrict__ x,
    const float* __restrict__ W,
    const float* __restrict__ bias,
    float2* __restrict__ out2)
{
    __shared__ float2 xs[NB * T_DIM];          // xs[b_l*24+t] = (x_f0, x_f1); float4-aliasable
    __shared__ float4 Wq[O_DIM * WPAD];        // Wq[o*13+j] = (W0[2j],W1[2j],W0[2j+1],W1[2j+1])
    __shared__ float2 bs[O_DIM];

    const int tid = threadIdx.x;
    const int b0  = blockIdx.x * NB;

    // ---- Phase 1a: gather x — one float2 per thread, every lane a distinct line.
    {
        const float2* __restrict__ x2 = (const float2*)x;
        int b_l = tid / T_DIM;
        int t   = tid - b_l * T_DIM;
        xs[tid] = x2[(size_t)((b0 + b_l) * T_DIM + t) * (F_DIM / 2)];
    }

    // ---- Phase 1b (overlapped): stage W into interleaved-pair float4 layout.
    // W layout (f,o,t): W0 at [o*24+t], W1 at [576 + o*24+t].
    #pragma unroll
    for (int j = tid; j < O_DIM * WJ; j += BLOCK) {
        int o  = j / WJ;
        int jj = j - o * WJ;              // float4 index -> t = 2jj, 2jj+1
        int t0 = 2 * jj;
        float4 v;
        v.x = W[o * T_DIM + t0];
        v.y = W[O_DIM * T_DIM + o * T_DIM + t0];
        v.z = W[o * T_DIM + t0 + 1];
        v.w = W[O_DIM * T_DIM + o * T_DIM + t0 + 1];
        Wq[o * WPAD + jj] = v;
    }
    if (tid < O_DIM)
        bs[tid] = make_float2(bias[tid], bias[O_DIM + tid]);
    __syncthreads();

    // ---- Phase 2: one float2 output per thread; 12+12 LDS.128 + 48 FMA.
    const int b_l = tid / O_DIM;
    const int o   = tid - b_l * O_DIM;

    const float4* __restrict__ xq = (const float4*)(xs + b_l * T_DIM);  // 12 float4, broadcast
    const float4* __restrict__ wq = Wq + o * WPAD;                      // stride-13 -> conflict-free

    float2 acc = bs[o];
    #pragma unroll
    for (int j = 0; j < WJ; j++) {
        float4 xv = xq[j];        // (x0[2j], x1[2j], x0[2j+1], x1[2j+1])
        float4 wv = wq[j];        // (w0[2j], w1[2j], w0[2j+1], w1[2j+1])
        acc.x = fmaf(xv.x, wv.x, acc.x);
        acc.y = fmaf(xv.y, wv.y, acc.y);
        acc.x = fmaf(xv.z, wv.z, acc.x);
        acc.y = fmaf(xv.w, wv.w, acc.y);
    }

    out2[(size_t)b0 * O_DIM + tid] = acc;   // coalesced STG.64
}

extern "C" void kernel_launch(void* const* d_in, const int* in_sizes, int n_in,
                              void* d_out, int out_size)
{
    const float* x    = (const float*)d_in[0];
    const float* W    = (const float*)d_in[1];
    const float* bias = (const float*)d_in[2];
    float2* out2 = (float2*)d_out;

    dlinear_kernel<<<GRID, BLOCK>>>(x, W, bias, out2);
}